// round 4
// baseline (speedup 1.0000x reference)
#include <cuda_runtime.h>

#define BATCH 32
#define NPROB 256
#define NW    32          // one warp per matrix
#define CP    8           // columns per thread
#define INF_F 1e9f

// order-preserving float<->uint encoding (a<b <=> enc(a)<enc(b))
__device__ __forceinline__ unsigned ford(float f) {
    unsigned u = __float_as_uint(f);
    return (u & 0x80000000u) ? ~u : (u | 0x80000000u);
}
__device__ __forceinline__ float forddec(unsigned e) {
    unsigned b = (e & 0x80000000u) ? (e ^ 0x80000000u) : ~e;
    return __uint_as_float(b);
}

__global__ void __launch_bounds__(NW, 1)
hungarian_warp(const float* __restrict__ pred,
               const float* __restrict__ gt,
               float* __restrict__ out,
               int write_totals)
{
    const int b = blockIdx.x;
    const int t = threadIdx.x;          // 0..31

    __shared__ float  u_sh[NPROB + 1];     // row potentials (1-based rows)
    __shared__ int    p_sh[NPROB + 1];     // p[j] = row matched to col j (1-based), 0=free
    __shared__ int    way_sh[NPROB + 1];
    __shared__ float  up_sh[NPROB + 1];    // u[p[j]], phase-static
    __shared__ float4 pp_sh[NPROB + 1];    // pred4[p[j]-1], phase-static
    __shared__ float4 pred_sh[NPROB];

    // stage pred rows as float4
    for (int k = t; k < NPROB; k += NW)
        pred_sh[k] = ((const float4*)pred)[(size_t)b * NPROB + k];
    for (int k = t; k < NPROB + 1; k += NW) { u_sh[k] = 0.0f; p_sh[k] = 0; }

    // this thread's 8 gt points (cols t*8+1 .. t*8+8, 1-based)
    float4 g[CP];
    #pragma unroll
    for (int k = 0; k < CP; k++)
        g[k] = ((const float4*)gt)[(size_t)b * NPROB + t * CP + k];

    float v[CP];
    #pragma unroll
    for (int k = 0; k < CP; k++) v[k] = 0.0f;

    __syncwarp();

    for (int i = 1; i <= NPROB; i++) {
        if (t == 0) p_sh[0] = i;
        __syncwarp();

        // phase-static gather: up[j] = u[p[j]], pp[j] = pred row of p[j]
        #pragma unroll
        for (int k = 0; k < CP; k++) {
            const int col = t * CP + k + 1;
            const int pj  = p_sh[col];
            up_sh[col] = u_sh[pj];                       // pj==0 -> u_sh[0]==0, never read
            pp_sh[col] = pred_sh[pj > 0 ? pj - 1 : 0];
        }
        if (t == 0) { up_sh[0] = u_sh[i]; pp_sh[0] = pred_sh[i - 1]; }

        float minv[CP], Smark[CP];
        int   rows[CP];
        unsigned usedm = 0;
        #pragma unroll
        for (int k = 0; k < CP; k++) { minv[k] = INF_F; Smark[k] = 0.0f; rows[k] = 0; }
        float S = 0.0f;                                  // running sum of deltas
        __syncwarp();

        int j0 = 0;
        int jfree;
        while (true) {
            // mark j0 used (owner lane records its row + prefix S)
            if (j0 >= t * CP + 1 && j0 <= t * CP + CP) {
                const int row = p_sh[j0];
                #pragma unroll
                for (int k = 0; k < CP; k++)
                    if (t * CP + k + 1 == j0) {
                        usedm |= (1u << k); rows[k] = row; Smark[k] = S; minv[k] = INF_F;
                    }
            }

            const float4 P  = pp_sh[j0];                 // broadcast
            const float  uu = up_sh[j0];

            #pragma unroll
            for (int k = 0; k < CP; k++) {
                float d0 = P.x - g[k].x, d1 = P.y - g[k].y;
                float d2 = P.z - g[k].z, d3 = P.w - g[k].w;
                float cur = sqrtf(d0 * d0 + d1 * d1 + d2 * d2 + d3 * d3) - uu - v[k];
                if (usedm & (1u << k)) cur = INF_F;
                if (cur < minv[k]) { minv[k] = cur; way_sh[t * CP + k + 1] = j0; }
            }

            // local min (ascending col => first-index tie-break within thread)
            float lm = minv[0]; int lc = t * CP + 1;
            #pragma unroll
            for (int k = 1; k < CP; k++)
                if (minv[k] < lm) { lm = minv[k]; lc = t * CP + k + 1; }

            // warp argmin via 2x hardware REDUX, exact first-index tie-break
            const unsigned enc  = ford(lm);
            const unsigned menc = __reduce_min_sync(0xffffffffu, enc);
            const unsigned cand = (enc == menc) ? (unsigned)lc : 0xffffffffu;
            const int   j1      = (int)__reduce_min_sync(0xffffffffu, cand);
            const float delta   = forddec(menc);

            S += delta;
            #pragma unroll
            for (int k = 0; k < CP; k++) minv[k] -= delta;

            j0 = j1;
            if (p_sh[j1] == 0) { jfree = j1; break; }
        }

        __syncwarp();
        // augment (serial walk, lane 0) + virtual-col-0 dual update
        if (t == 0) {
            int j = jfree;
            while (j) { const int jn = way_sh[j]; p_sh[j] = p_sh[jn]; j = jn; }
            u_sh[i] += S;
        }
        // deferred dual updates for used columns (rows are pairwise distinct)
        #pragma unroll
        for (int k = 0; k < CP; k++)
            if (usedm & (1u << k)) {
                const float d = S - Smark[k];
                u_sh[rows[k]] += d;
                v[k] -= d;
            }
        __syncwarp();
    }

    // epilogue: col4row[p[c]-1] = c-1 ; totals
    float s = 0.0f;
    #pragma unroll
    for (int k = 0; k < CP; k++) {
        const int col = t * CP + k;            // 0-based column
        const int r   = p_sh[col + 1] - 1;     // 0-based matched row
        out[(size_t)b * NPROB + r] = (float)col;
        if (write_totals) {
            const float4 P = pred_sh[r];
            float d0 = P.x - g[k].x, d1 = P.y - g[k].y;
            float d2 = P.z - g[k].z, d3 = P.w - g[k].w;
            s += sqrtf(d0 * d0 + d1 * d1 + d2 * d2 + d3 * d3);
        }
    }
    if (write_totals) {
        #pragma unroll
        for (int off = 16; off; off >>= 1)
            s += __shfl_xor_sync(0xffffffffu, s, off);
        if (t == 0) out[(size_t)BATCH * NPROB + b] = s;
    }
}

extern "C" void kernel_launch(void* const* d_in, const int* in_sizes, int n_in,
                              void* d_out, int out_size)
{
    const float* pred = (const float*)d_in[0];
    const float* gt   = (const float*)d_in[1];
    float* out        = (float*)d_out;
    const int wt      = (out_size >= BATCH * NPROB + BATCH) ? 1 : 0;
    hungarian_warp<<<BATCH, NW>>>(pred, gt, out, wt);
}

// round 6
// speedup vs baseline: 1.7292x; 1.7292x over previous
#include <cuda_runtime.h>

#define BATCH 32
#define NPROB 256
#define NT    256
#define INF_F 1e9f

// order-preserving float<->uint encoding (a<b <=> enc(a)<enc(b))
__device__ __forceinline__ unsigned ford(float f) {
    unsigned u = __float_as_uint(f);
    return (u & 0x80000000u) ? ~u : (u | 0x80000000u);
}
__device__ __forceinline__ float forddec(unsigned e) {
    unsigned b = (e & 0x80000000u) ? (e ^ 0x80000000u) : ~e;
    return __uint_as_float(b);
}

__global__ void __launch_bounds__(NT, 1)
hungarian_jv(const float* __restrict__ pred,
             const float* __restrict__ gt,
             float* __restrict__ out,
             int write_totals)
{
    const int b    = blockIdx.x;
    const int t    = threadIdx.x;        // 0..255, owns column c = t+1 (1-based)
    const int c    = t + 1;
    const int w    = t >> 5;
    const int lane = t & 31;

    __shared__ float4 pred_sh[NPROB];
    __shared__ float  u_sh[NPROB + 1];      // row potentials, 1-based
    __shared__ int    p_sh[NPROB + 1];      // p[j] = row matched to col j (1-based), 0=free
    __shared__ int    way_sh[NPROB + 1];
    __shared__ float  up_sh[NPROB + 1];     // u[p[j]], phase-static
    __shared__ float4 pp_sh[NPROB + 1];     // pred[p[j]-1], phase-static
    __shared__ unsigned long long red[2][8];// double-buffered warp results
    __shared__ int    rowowner[NPROB];      // greedy conflict resolution
    __shared__ int    freerows[NPROB];
    __shared__ int    nf_sh;
    __shared__ float  wsum[8];

    // ---- stage data ----
    pred_sh[t] = ((const float4*)pred)[(size_t)b * NPROB + t];
    const float4 gv = ((const float4*)gt)[(size_t)b * NPROB + t];
    u_sh[t] = 0.0f;
    p_sh[t] = 0;
    rowowner[t] = 0x7fffffff;
    if (t == 0) { u_sh[NPROB] = 0.0f; p_sh[NPROB] = 0; }
    __syncthreads();

    // ---- column reduction: v[c] = min_i cost[i,c] (min over squared dists) ----
    float msq = INF_F; int mrow = 0;
    for (int r = 0; r < NPROB; r++) {
        const float4 P = pred_sh[r];
        float d0 = P.x - gv.x, d1 = P.y - gv.y, d2 = P.z - gv.z, d3 = P.w - gv.w;
        float sq = d0 * d0 + d1 * d1 + d2 * d2 + d3 * d3;
        if (sq < msq) { msq = sq; mrow = r; }
    }
    float v_c = sqrtf(msq);                 // == min_i sqrt(sq) (sqrtf monotone)
    atomicMin(&rowowner[mrow], t);
    __syncthreads();
    if (rowowner[mrow] == t) p_sh[c] = mrow + 1;   // this column wins its min row
    __syncthreads();
    if (t == 0) {
        int n = 0;
        for (int r = 0; r < NPROB; r++)
            if (rowowner[r] == 0x7fffffff) freerows[n++] = r;
        nf_sh = n;
    }
    __syncthreads();
    const int nf = nf_sh;

    // ---- shortest augmenting path phases for free rows only ----
    for (int idx = 0; idx < nf; idx++) {
        const int i = freerows[idx] + 1;    // 1-based row

        // phase-static gather
        const int pj = p_sh[c];
        up_sh[c] = u_sh[pj];                       // pj==0 -> u_sh[0]==0, never used
        pp_sh[c] = pred_sh[pj > 0 ? pj - 1 : 0];
        if (t == 0) {
            p_sh[0]  = i;                          // virtual column 0 holds free row (FIX)
            up_sh[0] = u_sh[i];
            pp_sh[0] = pred_sh[i - 1];
        }

        float minv_c = INF_F, Smark_c = 0.0f, S = 0.0f;
        int   row_c = 0;
        bool  used_c = false;
        int   par = 0;
        __syncthreads();

        int j0 = 0, jfree;
        while (true) {
            if (c == j0) { used_c = true; row_c = p_sh[j0]; Smark_c = S; minv_c = INF_F; }

            const float4 P  = pp_sh[j0];           // smem broadcast
            const float  uu = up_sh[j0];
            float d0 = P.x - gv.x, d1 = P.y - gv.y, d2 = P.z - gv.z, d3 = P.w - gv.w;
            float cur = sqrtf(d0 * d0 + d1 * d1 + d2 * d2 + d3 * d3) - uu - v_c;
            if (used_c) cur = INF_F;
            if (cur < minv_c) { minv_c = cur; way_sh[c] = j0; }
            const float masked = used_c ? INF_F : minv_c;

            // warp argmin: hw REDUX + ballot first-lane tie-break (ascending cols)
            const unsigned enc  = ford(masked);
            const unsigned menc = __reduce_min_sync(0xffffffffu, enc);
            const unsigned bal  = __ballot_sync(0xffffffffu, enc == menc);
            const int      fl   = __ffs(bal) - 1;
            if (lane == 0)
                red[par][w] = (((unsigned long long)menc) << 32)
                            | (unsigned)(w * 32 + fl + 1);
            __syncthreads();

            // 8-way combine (broadcast reads, redundant in every thread)
            unsigned long long bk = red[par][0];
            #pragma unroll
            for (int q = 1; q < 8; q++) {
                unsigned long long o = red[par][q];
                if (o < bk) bk = o;
            }
            const int   j1    = (int)(bk & 0xffffffffu);
            const float delta = forddec((unsigned)(bk >> 32));

            S += delta;
            minv_c -= delta;
            const int pj1 = p_sh[j1];
            par ^= 1;
            j0 = j1;
            if (pj1 == 0) { jfree = j1; break; }
        }

        __syncthreads();
        // augment (lane-0 serial walk) + deferred dual updates
        if (t == 0) {
            int j = jfree;
            while (j) { const int jn = way_sh[j]; p_sh[j] = p_sh[jn]; j = jn; }
            u_sh[i] += S;
        }
        if (used_c) {                      // matched rows pairwise distinct, != i
            const float d = S - Smark_c;
            u_sh[row_c] += d;
            v_c -= d;
        }
        __syncthreads();
    }

    // ---- epilogue: col4row[p[c]-1] = c-1 ; per-batch total ----
    const int r = p_sh[c] - 1;
    out[(size_t)b * NPROB + r] = (float)t;

    if (write_totals) {
        const float4 P = pred_sh[r];
        float d0 = P.x - gv.x, d1 = P.y - gv.y, d2 = P.z - gv.z, d3 = P.w - gv.w;
        float mc = sqrtf(d0 * d0 + d1 * d1 + d2 * d2 + d3 * d3);
        #pragma unroll
        for (int off = 16; off; off >>= 1)
            mc += __shfl_xor_sync(0xffffffffu, mc, off);
        if (lane == 0) wsum[w] = mc;
        __syncthreads();
        if (t == 0) {
            float s = 0.0f;
            #pragma unroll
            for (int q = 0; q < 8; q++) s += wsum[q];
            out[(size_t)BATCH * NPROB + b] = s;
        }
    }
}

extern "C" void kernel_launch(void* const* d_in, const int* in_sizes, int n_in,
                              void* d_out, int out_size)
{
    const float* pred = (const float*)d_in[0];
    const float* gt   = (const float*)d_in[1];
    float* out        = (float*)d_out;
    const int wt      = (out_size >= BATCH * NPROB + BATCH) ? 1 : 0;
    hungarian_jv<<<BATCH, NT>>>(pred, gt, out, wt);
}

// round 7
// speedup vs baseline: 2.6163x; 1.5131x over previous
#include <cuda_runtime.h>

#define BATCH  32
#define NPROB  256
#define NT     128          // 4 warps
#define NWARP  4
#define CP     2            // columns per thread
#define INF_F  1e9f
#define ARR_CAP 1024
#define QCAP   (NPROB + ARR_CAP + 8)

// order-preserving float<->uint encoding (a<b <=> enc(a)<enc(b))
__device__ __forceinline__ unsigned ford(float f) {
    unsigned u = __float_as_uint(f);
    return (u & 0x80000000u) ? ~u : (u | 0x80000000u);
}
__device__ __forceinline__ float forddec(unsigned e) {
    unsigned b = (e & 0x80000000u) ? (e ^ 0x80000000u) : ~e;
    return __uint_as_float(b);
}
__device__ __forceinline__ float dist4(float4 P, float4 G) {
    float d0 = P.x - G.x, d1 = P.y - G.y, d2 = P.z - G.z, d3 = P.w - G.w;
    return sqrtf(d0 * d0 + d1 * d1 + d2 * d2 + d3 * d3);
}

__global__ void __launch_bounds__(NT, 1)
hungarian_jv(const float* __restrict__ pred,
             const float* __restrict__ gt,
             float* __restrict__ out,
             int write_totals)
{
    const int b    = blockIdx.x;
    const int t    = threadIdx.x;        // owns cols c0=2t+1, c1=2t+2 (1-based)
    const int w    = t >> 5;
    const int lane = t & 31;
    const int c0   = 2 * t + 1, c1 = 2 * t + 2;

    __shared__ float4 pred_sh[NPROB];
    __shared__ float  u_sh[NPROB + 1];
    __shared__ int    p_sh[NPROB + 1];      // p[j]=row matched to col j (1-based), 0=free
    __shared__ int    way_sh[NPROB + 1];
    __shared__ float  up_sh[NPROB + 1];
    __shared__ float4 pp_sh[NPROB + 1];
    __shared__ unsigned long long red[2][NWARP];
    __shared__ int    rowowner[NPROB];
    __shared__ int    freeq[QCAP];
    __shared__ int    head_sh, tail_sh;
    __shared__ float  wsum[NWARP];

    // ---- stage ----
    for (int k = t; k < NPROB; k += NT)
        pred_sh[k] = ((const float4*)pred)[(size_t)b * NPROB + k];
    float4 g[CP];
    g[0] = ((const float4*)gt)[(size_t)b * NPROB + 2 * t];
    g[1] = ((const float4*)gt)[(size_t)b * NPROB + 2 * t + 1];
    for (int k = t; k <= NPROB; k += NT) { u_sh[k] = 0.0f; p_sh[k] = 0; }
    for (int k = t; k < NPROB; k += NT) rowowner[k] = 0x7fffffff;
    __syncthreads();

    // ---- column reduction (min over squared dists; sqrtf monotone) ----
    float msq[CP] = {INF_F, INF_F}; int mrow[CP] = {0, 0};
    for (int r = 0; r < NPROB; r++) {
        const float4 P = pred_sh[r];
        #pragma unroll
        for (int k = 0; k < CP; k++) {
            float d0 = P.x - g[k].x, d1 = P.y - g[k].y;
            float d2 = P.z - g[k].z, d3 = P.w - g[k].w;
            float sq = d0 * d0 + d1 * d1 + d2 * d2 + d3 * d3;
            if (sq < msq[k]) { msq[k] = sq; mrow[k] = r; }
        }
    }
    float v[CP];
    #pragma unroll
    for (int k = 0; k < CP; k++) {
        v[k] = sqrtf(msq[k]);
        atomicMin(&rowowner[mrow[k]], 2 * t + k);
    }
    __syncthreads();
    #pragma unroll
    for (int k = 0; k < CP; k++)
        if (rowowner[mrow[k]] == 2 * t + k) p_sh[2 * t + k + 1] = mrow[k] + 1;
    __syncthreads();
    if (t == 0) {
        int n = 0;
        for (int r = 0; r < NPROB; r++)
            if (rowowner[r] == 0x7fffffff) freeq[n++] = r + 1;   // 1-based rows
        head_sh = 0; tail_sh = n;
    }
    __syncthreads();

    // ---- augmenting row reduction (JV ARR) ----
    int steps = 0;
    while (true) {
        const int head = head_sh, tail = tail_sh;
        if (head >= tail || steps >= ARR_CAP) break;
        steps++;
        const int i = freeq[head];
        const float4 P = pred_sh[i - 1];
        float rc[CP];
        #pragma unroll
        for (int k = 0; k < CP; k++) rc[k] = dist4(P, g[k]) - v[k];

        // min1 (value + smallest col among achievers)
        float lm = rc[0]; int lc = c0;
        if (rc[1] < lm) { lm = rc[1]; lc = c1; }
        unsigned enc  = ford(lm);
        unsigned menc = __reduce_min_sync(0xffffffffu, enc);
        unsigned cand = (enc == menc) ? (unsigned)lc : 0xffffffffu;
        unsigned jc   = __reduce_min_sync(0xffffffffu, cand);
        if (lane == 0) red[0][w] = (((unsigned long long)menc) << 32) | jc;
        __syncthreads();
        unsigned long long b1 = red[0][0];
        #pragma unroll
        for (int q = 1; q < NWARP; q++) { unsigned long long o = red[0][q]; if (o < b1) b1 = o; }
        const int   j1 = (int)(b1 & 0xffffffffu);
        const float u1 = forddec((unsigned)(b1 >> 32));

        // min2 excluding col j1
        float m0 = (c0 == j1) ? INF_F : rc[0];
        float m1 = (c1 == j1) ? INF_F : rc[1];
        float lm2 = m0; int lc2 = c0;
        if (m1 < lm2) { lm2 = m1; lc2 = c1; }
        unsigned enc2  = ford(lm2);
        unsigned menc2 = __reduce_min_sync(0xffffffffu, enc2);
        unsigned cand2 = (enc2 == menc2) ? (unsigned)lc2 : 0xffffffffu;
        unsigned jc2   = __reduce_min_sync(0xffffffffu, cand2);
        if (lane == 0) red[1][w] = (((unsigned long long)menc2) << 32) | jc2;
        __syncthreads();
        unsigned long long b2 = red[1][0];
        #pragma unroll
        for (int q = 1; q < NWARP; q++) { unsigned long long o = red[1][q]; if (o < b2) b2 = o; }
        const int   j2 = (int)(b2 & 0xffffffffu);
        const float u2 = forddec((unsigned)(b2 >> 32));

        const bool strict = (u1 < u2);
        // only the owner of col j1 touches v (register)
        if (strict) {
            if (j1 == c0) v[0] -= (u2 - u1);
            else if (j1 == c1) v[1] -= (u2 - u1);
        }
        // queue + assignment management on thread 0 only (sole p_sh toucher here)
        if (t == 0) {
            int jA = j1;
            if (!strict && p_sh[j1] != 0) jA = j2;
            const int i0 = p_sh[jA];
            p_sh[jA] = i;
            u_sh[i]  = u2;
            int nh = head + 1, nt2 = tail;
            if (i0 != 0) {
                if (strict) { nh = head; freeq[head] = i0; }  // reprocess next
                else        { freeq[nt2++] = i0; }            // append
            }
            head_sh = nh; tail_sh = nt2;
        }
        __syncthreads();
    }

    const int h0  = head_sh;
    const int t0q = tail_sh;

    // ---- shortest augmenting path phases for remaining free rows ----
    for (int idx = h0; idx < t0q; idx++) {
        const int i = freeq[idx];

        // phase-static gather: up[j]=u[p[j]], pp[j]=pred row of p[j]
        {
            int pj = p_sh[c0]; up_sh[c0] = u_sh[pj]; pp_sh[c0] = pred_sh[pj ? pj - 1 : 0];
            pj     = p_sh[c1]; up_sh[c1] = u_sh[pj]; pp_sh[c1] = pred_sh[pj ? pj - 1 : 0];
        }
        if (t == 0) { p_sh[0] = i; up_sh[0] = u_sh[i]; pp_sh[0] = pred_sh[i - 1]; }

        float minv[CP] = {INF_F, INF_F}, Smark[CP] = {0.0f, 0.0f};
        int   rows[CP] = {0, 0};
        unsigned usedm = 0;
        float S = 0.0f;
        int par = 0;
        __syncthreads();

        int j0 = 0, jfreecol;
        while (true) {
            if (j0 == c0)      { usedm |= 1u; rows[0] = p_sh[j0]; Smark[0] = S; minv[0] = INF_F; }
            else if (j0 == c1) { usedm |= 2u; rows[1] = p_sh[j0]; Smark[1] = S; minv[1] = INF_F; }

            const float4 P  = pp_sh[j0];          // smem broadcast
            const float  uu = up_sh[j0];
            #pragma unroll
            for (int k = 0; k < CP; k++) {
                float cur = dist4(P, g[k]) - uu - v[k];
                if (usedm & (1u << k)) cur = INF_F;
                if (cur < minv[k]) { minv[k] = cur; way_sh[2 * t + 1 + k] = j0; }
            }
            float lm = minv[0]; int lc = c0;
            if (minv[1] < lm) { lm = minv[1]; lc = c1; }

            unsigned enc  = ford(lm);
            unsigned menc = __reduce_min_sync(0xffffffffu, enc);
            unsigned cand = (enc == menc) ? (unsigned)lc : 0xffffffffu;
            unsigned jc   = __reduce_min_sync(0xffffffffu, cand);
            if (lane == 0) red[par][w] = (((unsigned long long)menc) << 32) | jc;
            __syncthreads();

            unsigned long long bk = red[par][0];
            #pragma unroll
            for (int q = 1; q < NWARP; q++) { unsigned long long o = red[par][q]; if (o < bk) bk = o; }
            const int   j1    = (int)(bk & 0xffffffffu);
            const float delta = forddec((unsigned)(bk >> 32));

            S += delta;
            minv[0] -= delta; minv[1] -= delta;
            const int pj1 = p_sh[j1];
            par ^= 1;
            j0 = j1;
            if (pj1 == 0) { jfreecol = j1; break; }
        }

        __syncthreads();
        if (t == 0) {
            int j = jfreecol;
            while (j) { const int jn = way_sh[j]; p_sh[j] = p_sh[jn]; j = jn; }
            u_sh[i] += S;
        }
        #pragma unroll
        for (int k = 0; k < CP; k++)
            if (usedm & (1u << k)) {
                const float d = S - Smark[k];
                u_sh[rows[k]] += d;     // matched rows pairwise distinct, != i
                v[k] -= d;
            }
        __syncthreads();
    }

    // ---- epilogue ----
    float s = 0.0f;
    #pragma unroll
    for (int k = 0; k < CP; k++) {
        const int col = 2 * t + k;                 // 0-based
        const int r   = p_sh[col + 1] - 1;         // 0-based matched row
        out[(size_t)b * NPROB + r] = (float)col;
        if (write_totals) s += dist4(pred_sh[r], g[k]);
    }
    if (write_totals) {
        #pragma unroll
        for (int off = 16; off; off >>= 1)
            s += __shfl_xor_sync(0xffffffffu, s, off);
        if (lane == 0) wsum[w] = s;
        __syncthreads();
        if (t == 0) {
            float acc = 0.0f;
            #pragma unroll
            for (int q = 0; q < NWARP; q++) acc += wsum[q];
            out[(size_t)BATCH * NPROB + b] = acc;
        }
    }
}

extern "C" void kernel_launch(void* const* d_in, const int* in_sizes, int n_in,
                              void* d_out, int out_size)
{
    const float* pred = (const float*)d_in[0];
    const float* gt   = (const float*)d_in[1];
    float* out        = (float*)d_out;
    const int wt      = (out_size >= BATCH * NPROB + BATCH) ? 1 : 0;
    hungarian_jv<<<BATCH, NT>>>(pred, gt, out, wt);
}